// round 4
// baseline (speedup 1.0000x reference)
#include <cuda_runtime.h>
#include <cuda_bf16.h>
#include <cstdint>

#define N_NODES 10000
#define N_EDGES 64000
#define N_GRAPHS 64
#define HID 64
#define ET 128                    // edges per GEMM tile
#define NTILES (N_EDGES / ET)     // 500
#define NSLICE 65                 // 64 w2 slices + 1 bias slice
#define BPAD 72                   // padded B row stride (floats), conflict-free
#define BSLICE (HID * BPAD)       // 4608 floats per prepped slice

// ---------------- scratch (device globals; no allocation allowed) ----------------
__device__ float g_h0[N_NODES * HID];
__device__ float g_h1[N_NODES * HID];
__device__ float g_agg[N_NODES * HID];
__device__ float g_tt1[NTILES * HID * ET];      // edge-MLP layer1: [tile][k][e]
__device__ float g_tt2[NTILES * HID * ET];      // edge-MLP layer2: [tile][k][e]
__device__ float g_bprep[2 * NSLICE * BSLICE];  // w2 (+bias) tf32, padded [layer][s][i][o]
__device__ int   g_src[N_EDGES];
__device__ int   g_dst[N_EDGES];
__device__ int   g_bat[N_NODES];
__device__ float g_hg[N_GRAPHS * HID];

__device__ __forceinline__ float lrelu(float v) { return v > 0.f ? v : 0.01f * v; }

// ---------------- PTX helpers ----------------
__device__ __forceinline__ void cp16(void* s, const void* g) {
    unsigned sa = (unsigned)__cvta_generic_to_shared(s);
    asm volatile("cp.async.cg.shared.global [%0], [%1], 16;" :: "r"(sa), "l"(g));
}
__device__ __forceinline__ void cp_commit() { asm volatile("cp.async.commit_group;"); }

__device__ __forceinline__ uint32_t tf32rn(float x) {
    uint32_t r;
    asm("cvt.rna.tf32.f32 %0, %1;" : "=r"(r) : "f"(x));
    return r;
}

__device__ __forceinline__ void mma8(float* c, const uint32_t* a, uint32_t b0, uint32_t b1) {
    asm volatile(
        "mma.sync.aligned.m16n8k8.row.col.f32.tf32.tf32.f32 "
        "{%0,%1,%2,%3}, {%4,%5,%6,%7}, {%8,%9}, {%0,%1,%2,%3};"
        : "+f"(c[0]), "+f"(c[1]), "+f"(c[2]), "+f"(c[3])
        : "r"(a[0]), "r"(a[1]), "r"(a[2]), "r"(a[3]), "r"(b0), "r"(b1));
}

// ---------------- index conversion (int64-vs-int32 auto-detect) ----------------
__global__ void convert_idx_kernel(const void* ei, const void* bat) {
    __shared__ int s64;
    if (threadIdx.x == 0) {
        const unsigned* w = (const unsigned*)ei;
        int z = 0;
        for (int i = 1; i < 256; i += 2) z += (w[i] == 0u);
        s64 = (z > 64);
    }
    __syncthreads();
    const bool is64 = (s64 != 0);
    int stride = blockDim.x * gridDim.x;
    for (int g = blockIdx.x * blockDim.x + threadIdx.x; g < N_EDGES; g += stride) {
        if (is64) {
            g_src[g] = (int)((const long long*)ei)[g];
            g_dst[g] = (int)((const long long*)ei)[N_EDGES + g];
        } else {
            g_src[g] = ((const int*)ei)[g];
            g_dst[g] = ((const int*)ei)[N_EDGES + g];
        }
    }
    for (int g = blockIdx.x * blockDim.x + threadIdx.x; g < N_NODES; g += stride) {
        g_bat[g] = is64 ? (int)((const long long*)bat)[g] : ((const int*)bat)[g];
    }
}

// ---------------- node encoder: h = lrelu(x @ W[128,64] + b) ----------------
__global__ void node_enc_kernel(const float* __restrict__ x, const float* __restrict__ w,
                                const float* __restrict__ b, float* __restrict__ h) {
    __shared__ float xs[16 * 128];
    __shared__ float ws[128 * 64];
    int tid = threadIdx.x;
    int n0 = blockIdx.x * 16;
    for (int idx = tid; idx < 16 * 128; idx += 256) xs[idx] = x[n0 * 128 + idx];
    for (int idx = tid; idx < 128 * 64; idx += 256) ws[idx] = w[idx];
    __syncthreads();
#pragma unroll
    for (int p = 0; p < 4; ++p) {
        int idx = p * 256 + tid;
        int o = idx & 63, nl = idx >> 6;
        float acc = b[o];
#pragma unroll 8
        for (int i = 0; i < 128; ++i) acc += xs[nl * 128 + i] * ws[i * 64 + o];
        h[n0 * 64 + idx] = lrelu(acc);
    }
}

// ---------------- fused edge MLP stage 1 (both layers): t = relu(ea @ W1 + b1) ----------------
__global__ void edge_mlp2_kernel(const float* __restrict__ ea,
                                 const float* __restrict__ w1a, const float* __restrict__ b1a,
                                 const float* __restrict__ w1b, const float* __restrict__ b1b,
                                 float* __restrict__ tt1, float* __restrict__ tt2) {
    __shared__ float eas[128 * 33];
    __shared__ float wA[32 * 64];
    __shared__ float wB[32 * 64];
    __shared__ float bA[64], bB[64];
    int tid = threadIdx.x;
    int tile = blockIdx.x;
    for (int idx = tid; idx < 128 * 32; idx += 256) {
        int e = idx >> 5, j = idx & 31;
        eas[e * 33 + j] = ea[tile * 4096 + idx];
    }
    for (int idx = tid; idx < 2048; idx += 256) { wA[idx] = w1a[idx]; wB[idx] = w1b[idx]; }
    if (tid < 64) { bA[tid] = b1a[tid]; bB[tid] = b1b[tid]; }
    __syncthreads();
#pragma unroll 4
    for (int p = 0; p < 32; ++p) {
        int idx = p * 256 + tid;
        int e = idx & 127, o = idx >> 7;
        float a1 = bA[o], a2 = bB[o];
#pragma unroll
        for (int j = 0; j < 32; ++j) {
            float v = eas[e * 33 + j];
            a1 += v * wA[j * 64 + o];
            a2 += v * wB[j * 64 + o];
        }
        tt1[tile * 8192 + o * 128 + e] = fmaxf(a1, 0.f);
        tt2[tile * 8192 + o * 128 + e] = fmaxf(a2, 0.f);
    }
}

__global__ void zero_kernel(float* p, int n) {
    int id = blockIdx.x * blockDim.x + threadIdx.x;
    if (id < n) p[id] = 0.f;
}

// ---------------- B prep (both layers): tf32-round w2 (+b2) into padded [s][i][o] ----------------
__global__ void bprep2_kernel(const float* __restrict__ w2a, const float* __restrict__ b2a,
                              const float* __restrict__ w2b, const float* __restrict__ b2b,
                              uint32_t* __restrict__ bp) {
    int id = blockIdx.x * blockDim.x + threadIdx.x;  // < 2*65*4096
    if (id >= 2 * NSLICE * 4096) return;
    int layer = id >= NSLICE * 4096;
    int rid = id - layer * NSLICE * 4096;
    int s = rid >> 12;
    int r = rid & 4095;
    int i = r >> 6, o = r & 63;
    const float* w2 = layer ? w2b : w2a;
    const float* b2 = layer ? b2b : b2a;
    float v = (s < 64) ? w2[(s << 12) + (i << 6) + o] : b2[(i << 6) + o];
    bp[(size_t)layer * NSLICE * BSLICE + s * BSLICE + i * BPAD + o] = tf32rn(v);
}

// ---------------- tf32 mma.sync message GEMM + direct gather + scatter ----------------
// C[128 e, 64 o] = sum_{k<65} diag(t_k) * H[src(e),:] @ B_k[64,64]   (t_64 = 1, B_64 = bias)
__global__ void __launch_bounds__(128, 3) msg_mma_kernel(
    const float* __restrict__ tt, const float* __restrict__ hnode,
    const uint32_t* __restrict__ bp, float* __restrict__ agg) {
    __shared__ uint32_t Bs[2][BSLICE];
    const int tid = threadIdx.x;
    const int w = tid >> 5, lane = tid & 31;
    const int g = lane >> 2, tig = lane & 3;
    const int tile = blockIdx.x;

    // prefetch B slice 0 (group 0)
    {
        const uint32_t* s = bp;
#pragma unroll
        for (int q = 0; q < 9; ++q) {
            int f = (tid + q * 128) * 4;
            cp16(&Bs[0][f], s + f);
        }
        cp_commit();
    }

    // H fragments gathered directly: h[m][r][kt*2+c] = hnode[src[e(m,r)]][kt*8 + c*4 + tig]
    float h[2][2][16];
    {
        const int ebase = tile * 128 + w * 32 + g;
#pragma unroll
        for (int m = 0; m < 2; ++m)
#pragma unroll
            for (int r = 0; r < 2; ++r) {
                const int e = ebase + m * 16 + r * 8;
                const float* hp = hnode + (size_t)g_src[e] * 64 + tig;
#pragma unroll
                for (int kt = 0; kt < 8; ++kt) {
                    h[m][r][kt * 2 + 0] = hp[kt * 8];
                    h[m][r][kt * 2 + 1] = hp[kt * 8 + 4];
                }
            }
    }

    float C[2][8][4];
#pragma unroll
    for (int m = 0; m < 2; ++m)
#pragma unroll
        for (int nt = 0; nt < 8; ++nt)
#pragma unroll
            for (int q = 0; q < 4; ++q) C[m][nt][q] = 0.f;

    const float* tbase = tt + (size_t)tile * 8192 + w * 32 + g;

    for (int k = 0; k < NSLICE; ++k) {
        const int b = k & 1;
        if (k < NSLICE - 1) {
            const uint32_t* s = bp + (size_t)(k + 1) * BSLICE;
            uint32_t* d = Bs[b ^ 1];
#pragma unroll
            for (int q = 0; q < 9; ++q) {
                int f = (tid + q * 128) * 4;
                cp16(d + f, s + f);
            }
            cp_commit();
            asm volatile("cp.async.wait_group 1;");
        } else {
            asm volatile("cp.async.wait_group 0;");
        }
        __syncthreads();

        float tk[4];
        if (k < 64) {
            const float* tp = tbase + k * 128;
            tk[0] = tp[0]; tk[1] = tp[8]; tk[2] = tp[16]; tk[3] = tp[24];
        } else {
            tk[0] = tk[1] = tk[2] = tk[3] = 1.f;
        }

        const uint32_t* B = Bs[b];
#pragma unroll
        for (int kt = 0; kt < 8; ++kt) {
            uint32_t a[2][4];
#pragma unroll
            for (int m = 0; m < 2; ++m) {
                a[m][0] = tf32rn(h[m][0][kt * 2 + 0] * tk[2 * m + 0]);
                a[m][1] = tf32rn(h[m][1][kt * 2 + 0] * tk[2 * m + 1]);
                a[m][2] = tf32rn(h[m][0][kt * 2 + 1] * tk[2 * m + 0]);
                a[m][3] = tf32rn(h[m][1][kt * 2 + 1] * tk[2 * m + 1]);
            }
            const uint32_t* Brow = B + (kt * 8 + tig) * BPAD + g;
#pragma unroll
            for (int nt = 0; nt < 8; ++nt) {
                uint32_t b0 = Brow[nt * 8];
                uint32_t b1 = Brow[nt * 8 + 4 * BPAD];
                mma8(C[0][nt], a[0], b0, b1);
                mma8(C[1][nt], a[1], b0, b1);
            }
        }
        __syncthreads();
    }

    // epilogue: scatter-add to agg[dst]
    const int ebase = tile * 128 + w * 32 + g;
#pragma unroll
    for (int m = 0; m < 2; ++m) {
        int d0 = g_dst[ebase + m * 16];
        int d1 = g_dst[ebase + m * 16 + 8];
        float* p0 = agg + (size_t)d0 * 64 + 2 * tig;
        float* p1 = agg + (size_t)d1 * 64 + 2 * tig;
#pragma unroll
        for (int nt = 0; nt < 8; ++nt) {
            atomicAdd(p0 + nt * 8 + 0, C[m][nt][0]);
            atomicAdd(p0 + nt * 8 + 1, C[m][nt][1]);
            atomicAdd(p1 + nt * 8 + 0, C[m][nt][2]);
            atomicAdd(p1 + nt * 8 + 1, C[m][nt][3]);
        }
    }
}

// ---------------- node update: h_out = lrelu(agg + h_in @ root + bias), optional pool ----------------
#define NUPD_NODES 64
__global__ void node_update_kernel(const float* __restrict__ hin, const float* __restrict__ agg,
                                   const float* __restrict__ root, const float* __restrict__ bias,
                                   float* __restrict__ hout, int do_pool) {
    __shared__ float rs[64 * 64];
    const int tid = threadIdx.x;
    const int o = tid & 63, q = tid >> 6;
    const int n0 = blockIdx.x * NUPD_NODES;
    for (int idx = tid; idx < 4096; idx += 256) rs[idx] = root[idx];
    __syncthreads();

    float run = 0.f;
    int curb = -1;
    for (int n = n0 + q; n < n0 + NUPD_NODES && n < N_NODES; n += 4) {
        float acc = bias[o] + agg[n * 64 + o];
        const float* hr = hin + (size_t)n * 64;
#pragma unroll 8
        for (int i = 0; i < 64; ++i) acc += hr[i] * rs[i * 64 + o];
        float v = lrelu(acc);
        hout[n * 64 + o] = v;
        if (do_pool) {
            int bn = g_bat[n];
            if (bn != curb) {
                if (curb >= 0) atomicAdd(&g_hg[curb * 64 + o], run);
                run = 0.f;
                curb = bn;
            }
            run += v;
        }
    }
    if (do_pool && curb >= 0) atomicAdd(&g_hg[curb * 64 + o], run);
}

// ---------------- readout head ----------------
__global__ void head_kernel(const float* __restrict__ fc1w, const float* __restrict__ fc1b,
                            const float* __restrict__ fc2w, const float* __restrict__ fc2b,
                            float* __restrict__ out) {
    __shared__ float hs[N_GRAPHS * HID];
    int g = threadIdx.x;
    for (int i = g; i < N_GRAPHS * HID; i += 64) hs[i] = g_hg[i];
    __syncthreads();
    float acc = fc2b[0];
#pragma unroll 4
    for (int j = 0; j < 32; ++j) {
        float s = fc1b[j];
#pragma unroll 8
        for (int i = 0; i < 64; ++i) s += hs[g * 64 + i] * fc1w[i * 32 + j];
        acc += lrelu(s) * fc2w[j];
    }
    out[g] = acc;
}

// ---------------- launch ----------------
extern "C" void kernel_launch(void* const* d_in, const int* in_sizes, int n_in,
                              void* d_out, int out_size) {
    const float* x     = (const float*)d_in[0];
    const void*  ei    = d_in[1];
    const float* ea    = (const float*)d_in[2];
    const void*  bat   = d_in[3];
    const float* nfc_w = (const float*)d_in[4];
    const float* nfc_b = (const float*)d_in[5];
    const float* e1w1  = (const float*)d_in[6];
    const float* e1b1  = (const float*)d_in[7];
    const float* e1w2  = (const float*)d_in[8];
    const float* e1b2  = (const float*)d_in[9];
    const float* root1 = (const float*)d_in[10];
    const float* bias1 = (const float*)d_in[11];
    const float* e2w1  = (const float*)d_in[12];
    const float* e2b1  = (const float*)d_in[13];
    const float* e2w2  = (const float*)d_in[14];
    const float* e2b2  = (const float*)d_in[15];
    const float* root2 = (const float*)d_in[16];
    const float* bias2 = (const float*)d_in[17];
    const float* fc1w  = (const float*)d_in[18];
    const float* fc1b  = (const float*)d_in[19];
    const float* fc2w  = (const float*)d_in[20];
    const float* fc2b  = (const float*)d_in[21];
    float* out = (float*)d_out;

    float *h0, *h1, *agg, *tt1, *tt2, *hg;
    uint32_t* bpp;
    cudaGetSymbolAddress((void**)&h0, g_h0);
    cudaGetSymbolAddress((void**)&h1, g_h1);
    cudaGetSymbolAddress((void**)&agg, g_agg);
    cudaGetSymbolAddress((void**)&tt1, g_tt1);
    cudaGetSymbolAddress((void**)&tt2, g_tt2);
    cudaGetSymbolAddress((void**)&hg, g_hg);
    cudaGetSymbolAddress((void**)&bpp, g_bprep);

    const int nupd_grid = (N_NODES + NUPD_NODES - 1) / NUPD_NODES;

    convert_idx_kernel<<<256, 256>>>(ei, bat);
    node_enc_kernel<<<N_NODES / 16, 256>>>(x, nfc_w, nfc_b, h0);
    edge_mlp2_kernel<<<NTILES, 256>>>(ea, e1w1, e1b1, e2w1, e2b1, tt1, tt2);
    bprep2_kernel<<<(2 * NSLICE * 4096 + 255) / 256, 256>>>(e1w2, e1b2, e2w2, e2b2, bpp);
    zero_kernel<<<(N_GRAPHS * HID + 255) / 256, 256>>>(hg, N_GRAPHS * HID);

    // layer 1
    zero_kernel<<<(N_NODES * HID + 255) / 256, 256>>>(agg, N_NODES * HID);
    msg_mma_kernel<<<NTILES, 128>>>(tt1, h0, bpp, agg);
    node_update_kernel<<<nupd_grid, 256>>>(h0, agg, root1, bias1, h1, 0);

    // layer 2 (pool fused into node update)
    zero_kernel<<<(N_NODES * HID + 255) / 256, 256>>>(agg, N_NODES * HID);
    msg_mma_kernel<<<NTILES, 128>>>(tt2, h1, bpp + (size_t)NSLICE * BSLICE, agg);
    node_update_kernel<<<nupd_grid, 256>>>(h1, agg, root2, bias2, h0, 1);

    head_kernel<<<1, 64>>>(fc1w, fc1b, fc2w, fc2b, out);
}

// round 5
// speedup vs baseline: 1.5335x; 1.5335x over previous
#include <cuda_runtime.h>
#include <cuda_bf16.h>
#include <cuda_fp16.h>
#include <cstdint>

#define N_NODES 10000
#define N_EDGES 64000
#define N_GRAPHS 64
#define HID 64
#define ET 128                    // edges per GEMM tile
#define NTILES (N_EDGES / ET)     // 500
#define NSLICE 65                 // 64 w2 slices + 1 bias slice
#define BPAD 72                   // padded B row stride (half2 units), conflict-free
#define BSLICE (32 * BPAD)        // 2304 half2 per prepped slice (32 i-pairs x 64 o)
#define BCHUNKS (BSLICE / 4)      // 576 16-byte chunks

// ---------------- scratch (device globals; no allocation allowed) ----------------
__device__ float g_h0[N_NODES * HID];
__device__ float g_h1[N_NODES * HID];
__device__ float g_agg[N_NODES * HID];
__device__ float g_tt[NTILES * HID * ET];        // edge-MLP output: [tile][k][e]
__device__ float g_hst[N_EDGES * HID];           // gathered h[src]: [e][i]
__device__ uint32_t g_bprep[2 * NSLICE * BSLICE];// w2 (+bias) fp16x2, padded [layer][s][i/2][o]
__device__ int   g_src[N_EDGES];
__device__ int   g_dst[N_EDGES];
__device__ int   g_bat[N_NODES];
__device__ float g_hg[N_GRAPHS * HID];

__device__ __forceinline__ float lrelu(float v) { return v > 0.f ? v : 0.01f * v; }

// ---------------- PTX helpers ----------------
__device__ __forceinline__ void cp16(void* s, const void* g) {
    unsigned sa = (unsigned)__cvta_generic_to_shared(s);
    asm volatile("cp.async.cg.shared.global [%0], [%1], 16;" :: "r"(sa), "l"(g));
}
__device__ __forceinline__ void cp_commit() { asm volatile("cp.async.commit_group;"); }

// fp16 mma: D[16x8] += A[16x16] * B[16x8]
__device__ __forceinline__ void mma16(float* c, const uint32_t* a, uint32_t b0, uint32_t b1) {
    asm volatile(
        "mma.sync.aligned.m16n8k16.row.col.f32.f16.f16.f32 "
        "{%0,%1,%2,%3}, {%4,%5,%6,%7}, {%8,%9}, {%0,%1,%2,%3};"
        : "+f"(c[0]), "+f"(c[1]), "+f"(c[2]), "+f"(c[3])
        : "r"(a[0]), "r"(a[1]), "r"(a[2]), "r"(a[3]), "r"(b0), "r"(b1));
}

// ---------------- index conversion (int64-vs-int32 auto-detect) ----------------
__global__ void convert_idx_kernel(const void* ei, const void* bat) {
    __shared__ int s64;
    if (threadIdx.x == 0) {
        const unsigned* w = (const unsigned*)ei;
        int z = 0;
        for (int i = 1; i < 256; i += 2) z += (w[i] == 0u);
        s64 = (z > 64);
    }
    __syncthreads();
    const bool is64 = (s64 != 0);
    int stride = blockDim.x * gridDim.x;
    for (int g = blockIdx.x * blockDim.x + threadIdx.x; g < N_EDGES; g += stride) {
        if (is64) {
            g_src[g] = (int)((const long long*)ei)[g];
            g_dst[g] = (int)((const long long*)ei)[N_EDGES + g];
        } else {
            g_src[g] = ((const int*)ei)[g];
            g_dst[g] = ((const int*)ei)[N_EDGES + g];
        }
    }
    for (int g = blockIdx.x * blockDim.x + threadIdx.x; g < N_NODES; g += stride) {
        g_bat[g] = is64 ? (int)((const long long*)bat)[g] : ((const int*)bat)[g];
    }
}

// ---------------- node encoder: h = lrelu(x @ W[128,64] + b) ----------------
__global__ void node_enc_kernel(const float* __restrict__ x, const float* __restrict__ w,
                                const float* __restrict__ b, float* __restrict__ h) {
    __shared__ float xs[16 * 128];
    __shared__ float ws[128 * 64];
    int tid = threadIdx.x;
    int n0 = blockIdx.x * 16;
    for (int idx = tid; idx < 16 * 128; idx += 256) xs[idx] = x[n0 * 128 + idx];
    for (int idx = tid; idx < 128 * 64; idx += 256) ws[idx] = w[idx];
    __syncthreads();
#pragma unroll
    for (int p = 0; p < 4; ++p) {
        int idx = p * 256 + tid;
        int o = idx & 63, nl = idx >> 6;
        float acc = b[o];
#pragma unroll 8
        for (int i = 0; i < 128; ++i) acc += xs[nl * 128 + i] * ws[i * 64 + o];
        h[n0 * 64 + idx] = lrelu(acc);
    }
}

// ---------------- edge MLP stage 1: t = relu(ea @ W1[32,64] + b1) -> [tile][k][e] ----------------
__global__ void edge_mlp_kernel(const float* __restrict__ ea, const float* __restrict__ w1,
                                const float* __restrict__ b1, float* __restrict__ tt) {
    __shared__ float eas[128 * 33];
    __shared__ float w1s[32 * 64];
    __shared__ float b1s[64];
    int tid = threadIdx.x;
    int tile = blockIdx.x;
    for (int idx = tid; idx < 128 * 32; idx += 256) {
        int e = idx >> 5, j = idx & 31;
        eas[e * 33 + j] = ea[tile * 4096 + idx];
    }
    for (int idx = tid; idx < 2048; idx += 256) w1s[idx] = w1[idx];
    if (tid < 64) b1s[tid] = b1[tid];
    __syncthreads();
#pragma unroll 4
    for (int p = 0; p < 32; ++p) {
        int idx = p * 256 + tid;
        int e = idx & 127, o = idx >> 7;
        float acc = b1s[o];
#pragma unroll
        for (int j = 0; j < 32; ++j) acc += eas[e * 33 + j] * w1s[j * 64 + o];
        tt[tile * 8192 + o * 128 + e] = fmaxf(acc, 0.f);
    }
}

// ---------------- gather h[src] into e-major layout [e][i] ----------------
__global__ void gather_kernel(const float* __restrict__ h, float* __restrict__ hst) {
    int id = blockIdx.x * blockDim.x + threadIdx.x;  // < N_EDGES*HID
    int i = id & 63;
    int e = id >> 6;
    hst[id] = h[g_src[e] * HID + i];
}

__global__ void zero_kernel(float* p, int n) {
    int id = blockIdx.x * blockDim.x + threadIdx.x;
    if (id < n) p[id] = 0.f;
}

// ---------------- B prep (both layers): w2 (+b2) -> half2-packed padded [s][i/2][o] ----------------
__global__ void bprep2_kernel(const float* __restrict__ w2a, const float* __restrict__ b2a,
                              const float* __restrict__ w2b, const float* __restrict__ b2b,
                              uint32_t* __restrict__ bp) {
    int id = blockIdx.x * blockDim.x + threadIdx.x;  // < 2*65*2048
    if (id >= 2 * NSLICE * 2048) return;
    int layer = id >= NSLICE * 2048;
    int rid = id - layer * NSLICE * 2048;
    int s = rid >> 11;
    int r = rid & 2047;
    int p = r >> 6, o = r & 63;
    const float* w2 = layer ? w2b : w2a;
    const float* b2 = layer ? b2b : b2a;
    int i0 = 2 * p, i1 = 2 * p + 1;
    float v0 = (s < 64) ? w2[(s << 12) + (i0 << 6) + o] : b2[(i0 << 6) + o];
    float v1 = (s < 64) ? w2[(s << 12) + (i1 << 6) + o] : b2[(i1 << 6) + o];
    __half2 hv = __floats2half2_rn(v0, v1);
    bp[(size_t)layer * NSLICE * BSLICE + s * BSLICE + p * BPAD + o] =
        *reinterpret_cast<uint32_t*>(&hv);
}

// ---------------- fp16 mma.sync message GEMM + scatter ----------------
// C[128 e, 64 o] = sum_{k<65} diag(t_k) * H[128,64] @ B_k[64,64]   (t_64 = 1, B_64 = bias)
__global__ void __launch_bounds__(128, 3) msg_mma_kernel(
    const float* __restrict__ tt, const float* __restrict__ hst,
    const uint32_t* __restrict__ bp, float* __restrict__ agg) {
    __shared__ uint32_t Bs[2][BSLICE];
    const int tid = threadIdx.x;
    const int w = tid >> 5, lane = tid & 31;
    const int g = lane >> 2, tig = lane & 3;
    const int tile = blockIdx.x;

    // prefetch B slice 0
    {
#pragma unroll
        for (int q = 0; q < 5; ++q) {
            int c = tid + q * 128;
            if (c < BCHUNKS) cp16(&Bs[0][c * 4], bp + c * 4);
        }
        cp_commit();
    }

    // H tile into half2 registers: hh[m][r][j] = (H[row][2tig+8j], H[row][2tig+8j+1]),
    // row = w*32 + m*16 + r*8 + g
    __half2 hh[2][2][8];
    {
        const float* hb = hst + ((size_t)tile * 128 + w * 32 + g) * 64 + 2 * tig;
#pragma unroll
        for (int m = 0; m < 2; ++m)
#pragma unroll
            for (int r = 0; r < 2; ++r) {
                const float* hp = hb + (m * 16 + r * 8) * 64;
#pragma unroll
                for (int j = 0; j < 8; ++j) {
                    float2 v = *(const float2*)(hp + 8 * j);
                    hh[m][r][j] = __floats2half2_rn(v.x, v.y);
                }
            }
    }

    float C[2][8][4];
#pragma unroll
    for (int m = 0; m < 2; ++m)
#pragma unroll
        for (int nt = 0; nt < 8; ++nt)
#pragma unroll
            for (int q = 0; q < 4; ++q) C[m][nt][q] = 0.f;

    const float* tbase = tt + (size_t)tile * 8192 + w * 32 + g;

    for (int k = 0; k < NSLICE; ++k) {
        const int b = k & 1;
        if (k < NSLICE - 1) {
            const uint32_t* s = bp + (size_t)(k + 1) * BSLICE;
            uint32_t* d = Bs[b ^ 1];
#pragma unroll
            for (int q = 0; q < 5; ++q) {
                int c = tid + q * 128;
                if (c < BCHUNKS) cp16(&d[c * 4], s + c * 4);
            }
            cp_commit();
            asm volatile("cp.async.wait_group 1;");
        } else {
            asm volatile("cp.async.wait_group 0;");
        }
        __syncthreads();

        // per-row t scales as half2 broadcast: t2[2m+r] for row m*16+r*8+g
        __half2 t2[4];
        if (k < 64) {
            const float* tp = tbase + k * 128;
            t2[0] = __float2half2_rn(tp[0]);
            t2[1] = __float2half2_rn(tp[8]);
            t2[2] = __float2half2_rn(tp[16]);
            t2[3] = __float2half2_rn(tp[24]);
        } else {
            t2[0] = t2[1] = t2[2] = t2[3] = __float2half2_rn(1.f);
        }

        const uint32_t* B = Bs[b];
#pragma unroll
        for (int kt = 0; kt < 4; ++kt) {
            __half2 a[2][4];
#pragma unroll
            for (int m = 0; m < 2; ++m) {
                a[m][0] = __hmul2(hh[m][0][2 * kt + 0], t2[2 * m + 0]);
                a[m][1] = __hmul2(hh[m][1][2 * kt + 0], t2[2 * m + 1]);
                a[m][2] = __hmul2(hh[m][0][2 * kt + 1], t2[2 * m + 0]);
                a[m][3] = __hmul2(hh[m][1][2 * kt + 1], t2[2 * m + 1]);
            }
            const uint32_t* Brow = B + (kt * 8 + tig) * BPAD + g;
#pragma unroll
            for (int nt = 0; nt < 8; ++nt) {
                uint32_t b0 = Brow[nt * 8];
                uint32_t b1 = Brow[nt * 8 + 4 * BPAD];
                mma16(C[0][nt], reinterpret_cast<const uint32_t*>(a[0]), b0, b1);
                mma16(C[1][nt], reinterpret_cast<const uint32_t*>(a[1]), b0, b1);
            }
        }
        __syncthreads();
    }

    // epilogue: scatter-add to agg[dst]
    const int ebase = tile * 128 + w * 32 + g;
#pragma unroll
    for (int m = 0; m < 2; ++m) {
        int d0 = g_dst[ebase + m * 16];
        int d1 = g_dst[ebase + m * 16 + 8];
        float* p0 = agg + (size_t)d0 * 64 + 2 * tig;
        float* p1 = agg + (size_t)d1 * 64 + 2 * tig;
#pragma unroll
        for (int nt = 0; nt < 8; ++nt) {
            atomicAdd(p0 + nt * 8 + 0, C[m][nt][0]);
            atomicAdd(p0 + nt * 8 + 1, C[m][nt][1]);
            atomicAdd(p1 + nt * 8 + 0, C[m][nt][2]);
            atomicAdd(p1 + nt * 8 + 1, C[m][nt][3]);
        }
    }
}

// ---------------- node update: h_out = lrelu(agg + h_in @ root + bias) ----------------
__global__ void node_update_kernel(const float* __restrict__ hin, const float* __restrict__ agg,
                                   const float* __restrict__ root, const float* __restrict__ bias,
                                   float* __restrict__ hout) {
    int id = blockIdx.x * blockDim.x + threadIdx.x;
    if (id >= N_NODES * HID) return;
    int n = id >> 6, o = id & 63;
    float acc = bias[o] + agg[id];
    const float* hr = hin + (size_t)n * 64;
#pragma unroll 8
    for (int i = 0; i < 64; ++i) acc += hr[i] * root[i * 64 + o];
    hout[id] = lrelu(acc);
}

// ---------------- global add pool ----------------
__global__ void pool_kernel(const float* __restrict__ h) {
    int id = blockIdx.x * blockDim.x + threadIdx.x;
    if (id >= N_NODES * HID) return;
    int n = id >> 6, o = id & 63;
    atomicAdd(&g_hg[g_bat[n] * 64 + o], h[id]);
}

// ---------------- readout head ----------------
__global__ void head_kernel(const float* __restrict__ fc1w, const float* __restrict__ fc1b,
                            const float* __restrict__ fc2w, const float* __restrict__ fc2b,
                            float* __restrict__ out) {
    __shared__ float hs[N_GRAPHS * HID];
    int g = threadIdx.x;
    for (int i = g; i < N_GRAPHS * HID; i += 64) hs[i] = g_hg[i];
    __syncthreads();
    float acc = fc2b[0];
#pragma unroll 4
    for (int j = 0; j < 32; ++j) {
        float s = fc1b[j];
#pragma unroll 8
        for (int i = 0; i < 64; ++i) s += hs[g * 64 + i] * fc1w[i * 32 + j];
        acc += lrelu(s) * fc2w[j];
    }
    out[g] = acc;
}

// ---------------- launch ----------------
extern "C" void kernel_launch(void* const* d_in, const int* in_sizes, int n_in,
                              void* d_out, int out_size) {
    const float* x     = (const float*)d_in[0];
    const void*  ei    = d_in[1];
    const float* ea    = (const float*)d_in[2];
    const void*  bat   = d_in[3];
    const float* nfc_w = (const float*)d_in[4];
    const float* nfc_b = (const float*)d_in[5];
    const float* e1w1  = (const float*)d_in[6];
    const float* e1b1  = (const float*)d_in[7];
    const float* e1w2  = (const float*)d_in[8];
    const float* e1b2  = (const float*)d_in[9];
    const float* root1 = (const float*)d_in[10];
    const float* bias1 = (const float*)d_in[11];
    const float* e2w1  = (const float*)d_in[12];
    const float* e2b1  = (const float*)d_in[13];
    const float* e2w2  = (const float*)d_in[14];
    const float* e2b2  = (const float*)d_in[15];
    const float* root2 = (const float*)d_in[16];
    const float* bias2 = (const float*)d_in[17];
    const float* fc1w  = (const float*)d_in[18];
    const float* fc1b  = (const float*)d_in[19];
    const float* fc2w  = (const float*)d_in[20];
    const float* fc2b  = (const float*)d_in[21];
    float* out = (float*)d_out;

    float *h0, *h1, *agg, *tt, *hst, *hg;
    uint32_t* bpp;
    cudaGetSymbolAddress((void**)&h0, g_h0);
    cudaGetSymbolAddress((void**)&h1, g_h1);
    cudaGetSymbolAddress((void**)&agg, g_agg);
    cudaGetSymbolAddress((void**)&tt, g_tt);
    cudaGetSymbolAddress((void**)&hst, g_hst);
    cudaGetSymbolAddress((void**)&hg, g_hg);
    cudaGetSymbolAddress((void**)&bpp, g_bprep);

    convert_idx_kernel<<<256, 256>>>(ei, bat);
    node_enc_kernel<<<N_NODES / 16, 256>>>(x, nfc_w, nfc_b, h0);
    bprep2_kernel<<<(2 * NSLICE * 2048 + 255) / 256, 256>>>(e1w2, e1b2, e2w2, e2b2, bpp);

    // layer 1
    edge_mlp_kernel<<<NTILES, 256>>>(ea, e1w1, e1b1, tt);
    gather_kernel<<<N_EDGES * HID / 256, 256>>>(h0, hst);
    zero_kernel<<<(N_NODES * HID + 255) / 256, 256>>>(agg, N_NODES * HID);
    msg_mma_kernel<<<NTILES, 128>>>(tt, hst, bpp, agg);
    node_update_kernel<<<(N_NODES * HID + 255) / 256, 256>>>(h0, agg, root1, bias1, h1);

    // layer 2
    edge_mlp_kernel<<<NTILES, 256>>>(ea, e2w1, e2b1, tt);
    gather_kernel<<<N_EDGES * HID / 256, 256>>>(h1, hst);
    zero_kernel<<<(N_NODES * HID + 255) / 256, 256>>>(agg, N_NODES * HID);
    msg_mma_kernel<<<NTILES, 128>>>(tt, hst, bpp + (size_t)NSLICE * BSLICE, agg);
    node_update_kernel<<<(N_NODES * HID + 255) / 256, 256>>>(h1, agg, root2, bias2, h0);

    // pool + head
    zero_kernel<<<(N_GRAPHS * HID + 255) / 256, 256>>>(hg, N_GRAPHS * HID);
    pool_kernel<<<(N_NODES * HID + 255) / 256, 256>>>(h0);
    head_kernel<<<1, 64>>>(fc1w, fc1b, fc2w, fc2b, out);
}

// round 6
// speedup vs baseline: 1.5882x; 1.0357x over previous
#include <cuda_runtime.h>
#include <cuda_bf16.h>
#include <cuda_fp16.h>
#include <cstdint>

#define N_NODES 10000
#define N_EDGES 64000
#define N_GRAPHS 64
#define HID 64
#define ET 128                    // edges per GEMM subtile
#define NTILES (N_EDGES / ET)     // 500 subtiles; 250 CTAs x 2
#define NSLICE 65                 // 64 w2 slices + 1 bias slice
#define BPAD 72                   // padded B row stride (half2 units), conflict-free
#define BSLICE (32 * BPAD)        // 2304 half2 per prepped slice
#define BCHUNKS (BSLICE / 4)      // 576 16-byte chunks

// ---------------- scratch (device globals; no allocation allowed) ----------------
__device__ float    g_h0[N_NODES * HID];
__device__ float    g_h1[N_NODES * HID];
__device__ float    g_agg[N_NODES * HID];
__device__ float    g_tt1[NTILES * HID * ET];     // edge-MLP layer1: [subtile][k][e]
__device__ float    g_tt2[NTILES * HID * ET];     // edge-MLP layer2: [subtile][k][e]
__device__ uint32_t g_hsth[N_EDGES * 32];         // gathered h[src] as half2: [e][i/2]
__device__ uint32_t g_bprep[2 * NSLICE * BSLICE]; // w2 (+bias) fp16x2, padded [layer][s][i/2][o]
__device__ int      g_src[N_EDGES];
__device__ int      g_dst[N_EDGES];
__device__ int      g_bat[N_NODES];
__device__ float    g_hg[N_GRAPHS * HID];

__device__ __forceinline__ float lrelu(float v) { return v > 0.f ? v : 0.01f * v; }

// ---------------- PTX helpers ----------------
__device__ __forceinline__ void cp16(void* s, const void* g) {
    unsigned sa = (unsigned)__cvta_generic_to_shared(s);
    asm volatile("cp.async.cg.shared.global [%0], [%1], 16;" :: "r"(sa), "l"(g));
}
__device__ __forceinline__ void cp_commit() { asm volatile("cp.async.commit_group;"); }

// fp16 mma: D[16x8] += A[16x16] * B[16x8]
__device__ __forceinline__ void mma16(float* c, const uint32_t* a, uint32_t b0, uint32_t b1) {
    asm volatile(
        "mma.sync.aligned.m16n8k16.row.col.f32.f16.f16.f32 "
        "{%0,%1,%2,%3}, {%4,%5,%6,%7}, {%8,%9}, {%0,%1,%2,%3};"
        : "+f"(c[0]), "+f"(c[1]), "+f"(c[2]), "+f"(c[3])
        : "r"(a[0]), "r"(a[1]), "r"(a[2]), "r"(a[3]), "r"(b0), "r"(b1));
}

// ---------------- index conversion (int64-vs-int32 auto-detect) ----------------
__global__ void convert_idx_kernel(const void* ei, const void* bat) {
    __shared__ int s64;
    if (threadIdx.x == 0) {
        const unsigned* w = (const unsigned*)ei;
        int z = 0;
        for (int i = 1; i < 256; i += 2) z += (w[i] == 0u);
        s64 = (z > 64);
    }
    __syncthreads();
    const bool is64 = (s64 != 0);
    int stride = blockDim.x * gridDim.x;
    for (int g = blockIdx.x * blockDim.x + threadIdx.x; g < N_EDGES; g += stride) {
        if (is64) {
            g_src[g] = (int)((const long long*)ei)[g];
            g_dst[g] = (int)((const long long*)ei)[N_EDGES + g];
        } else {
            g_src[g] = ((const int*)ei)[g];
            g_dst[g] = ((const int*)ei)[N_EDGES + g];
        }
    }
    for (int g = blockIdx.x * blockDim.x + threadIdx.x; g < N_NODES; g += stride) {
        g_bat[g] = is64 ? (int)((const long long*)bat)[g] : ((const int*)bat)[g];
    }
}

// ---------------- node encoder: h = lrelu(x @ W[128,64] + b) ----------------
__global__ void node_enc_kernel(const float* __restrict__ x, const float* __restrict__ w,
                                const float* __restrict__ b, float* __restrict__ h) {
    __shared__ float xs[16 * 128];
    __shared__ float ws[128 * 64];
    int tid = threadIdx.x;
    int n0 = blockIdx.x * 16;
    for (int idx = tid; idx < 16 * 128; idx += 256) xs[idx] = x[n0 * 128 + idx];
    for (int idx = tid; idx < 128 * 64; idx += 256) ws[idx] = w[idx];
    __syncthreads();
#pragma unroll
    for (int p = 0; p < 4; ++p) {
        int idx = p * 256 + tid;
        int o = idx & 63, nl = idx >> 6;
        float acc = b[o];
#pragma unroll 8
        for (int i = 0; i < 128; ++i) acc += xs[nl * 128 + i] * ws[i * 64 + o];
        h[n0 * 64 + idx] = lrelu(acc);
    }
}

// ---------------- fused edge MLP (both layers): t = relu(ea @ W1 + b1) ----------------
__global__ void edge_mlp2_kernel(const float* __restrict__ ea,
                                 const float* __restrict__ w1a, const float* __restrict__ b1a,
                                 const float* __restrict__ w1b, const float* __restrict__ b1b,
                                 float* __restrict__ tt1, float* __restrict__ tt2) {
    __shared__ float eas[128 * 33];
    __shared__ float wA[32 * 64];
    __shared__ float wB[32 * 64];
    __shared__ float bA[64], bB[64];
    int tid = threadIdx.x;
    int tile = blockIdx.x;
    for (int idx = tid; idx < 128 * 32; idx += 256) {
        int e = idx >> 5, j = idx & 31;
        eas[e * 33 + j] = ea[tile * 4096 + idx];
    }
    for (int idx = tid; idx < 2048; idx += 256) { wA[idx] = w1a[idx]; wB[idx] = w1b[idx]; }
    if (tid < 64) { bA[tid] = b1a[tid]; bB[tid] = b1b[tid]; }
    __syncthreads();
#pragma unroll 4
    for (int p = 0; p < 32; ++p) {
        int idx = p * 256 + tid;
        int e = idx & 127, o = idx >> 7;
        float a1 = bA[o], a2 = bB[o];
#pragma unroll
        for (int j = 0; j < 32; ++j) {
            float v = eas[e * 33 + j];
            a1 += v * wA[j * 64 + o];
            a2 += v * wB[j * 64 + o];
        }
        tt1[tile * 8192 + o * 128 + e] = fmaxf(a1, 0.f);
        tt2[tile * 8192 + o * 128 + e] = fmaxf(a2, 0.f);
    }
}

// ---------------- gather h[src] into e-major half2 layout [e][i/2] ----------------
__global__ void gather_kernel(const float* __restrict__ h, uint32_t* __restrict__ hsth) {
    int id = blockIdx.x * blockDim.x + threadIdx.x;  // < N_EDGES*32
    int p = id & 31;
    int e = id >> 5;
    float2 v = *(const float2*)(h + (size_t)g_src[e] * HID + 2 * p);
    __half2 hv = __floats2half2_rn(v.x, v.y);
    hsth[id] = *reinterpret_cast<uint32_t*>(&hv);
}

__global__ void zero_kernel(float* p, int n) {
    int id = blockIdx.x * blockDim.x + threadIdx.x;
    if (id < n) p[id] = 0.f;
}

// ---------------- B prep (both layers): w2 (+b2) -> half2-packed padded [s][i/2][o] ----------------
__global__ void bprep2_kernel(const float* __restrict__ w2a, const float* __restrict__ b2a,
                              const float* __restrict__ w2b, const float* __restrict__ b2b,
                              uint32_t* __restrict__ bp) {
    int id = blockIdx.x * blockDim.x + threadIdx.x;  // < 2*65*2048
    if (id >= 2 * NSLICE * 2048) return;
    int layer = id >= NSLICE * 2048;
    int rid = id - layer * NSLICE * 2048;
    int s = rid >> 11;
    int r = rid & 2047;
    int p = r >> 6, o = r & 63;
    const float* w2 = layer ? w2b : w2a;
    const float* b2 = layer ? b2b : b2a;
    int i0 = 2 * p, i1 = 2 * p + 1;
    float v0 = (s < 64) ? w2[(s << 12) + (i0 << 6) + o] : b2[(i0 << 6) + o];
    float v1 = (s < 64) ? w2[(s << 12) + (i1 << 6) + o] : b2[(i1 << 6) + o];
    __half2 hv = __floats2half2_rn(v0, v1);
    bp[(size_t)layer * NSLICE * BSLICE + s * BSLICE + p * BPAD + o] =
        *reinterpret_cast<uint32_t*>(&hv);
}

// ---------------- fp16 mma.sync message GEMM + scatter (256 edges / CTA, 8 warps) ----------------
// C[e, o] = sum_{k<65} diag(t_k) * H[...] @ B_k[64,64]   (t_64 = 1, B_64 = bias)
__global__ void __launch_bounds__(256, 2) msg_mma_kernel(
    const float* __restrict__ tt, const uint32_t* __restrict__ hsth,
    const uint32_t* __restrict__ bp, float* __restrict__ agg) {
    __shared__ uint32_t Bs[2][BSLICE];
    const int tid = threadIdx.x;
    const int w = tid >> 5, lane = tid & 31;
    const int g = lane >> 2, tig = lane & 3;
    const int subtile = 2 * blockIdx.x + (w >> 2);  // warps 0-3 -> subtile 2b, 4-7 -> 2b+1
    const int wl = w & 3;

    // prefetch B slice 0
    {
#pragma unroll
        for (int q = 0; q < 3; ++q) {
            int c = tid + q * 256;
            if (c < BCHUNKS) cp16(&Bs[0][c * 4], bp + c * 4);
        }
        cp_commit();
    }

    // H tile (half2) into registers: hh[m][r][j] = H2[row][tig + 4j], row = wl*32+m*16+r*8+g
    uint32_t hh[2][2][8];
    {
        const uint32_t* hb = hsth + ((size_t)subtile * 128 + wl * 32 + g) * 32 + tig;
#pragma unroll
        for (int m = 0; m < 2; ++m)
#pragma unroll
            for (int r = 0; r < 2; ++r) {
                const uint32_t* hp = hb + (m * 16 + r * 8) * 32;
#pragma unroll
                for (int j = 0; j < 8; ++j) hh[m][r][j] = hp[4 * j];
            }
    }

    float C[2][8][4];
#pragma unroll
    for (int m = 0; m < 2; ++m)
#pragma unroll
        for (int nt = 0; nt < 8; ++nt)
#pragma unroll
            for (int q = 0; q < 4; ++q) C[m][nt][q] = 0.f;

    const float* tbase = tt + (size_t)subtile * 8192 + wl * 32 + g;

    for (int k = 0; k < NSLICE; ++k) {
        const int b = k & 1;
        if (k < NSLICE - 1) {
            const uint32_t* s = bp + (size_t)(k + 1) * BSLICE;
            uint32_t* d = Bs[b ^ 1];
#pragma unroll
            for (int q = 0; q < 3; ++q) {
                int c = tid + q * 256;
                if (c < BCHUNKS) cp16(&d[c * 4], s + c * 4);
            }
            cp_commit();
            asm volatile("cp.async.wait_group 1;");
        } else {
            asm volatile("cp.async.wait_group 0;");
        }
        __syncthreads();

        // per-row t scales as half2 broadcast: t2[2m+r] for row m*16+r*8+g
        __half2 t2[4];
        if (k < 64) {
            const float* tp = tbase + k * 128;
            t2[0] = __float2half2_rn(tp[0]);
            t2[1] = __float2half2_rn(tp[8]);
            t2[2] = __float2half2_rn(tp[16]);
            t2[3] = __float2half2_rn(tp[24]);
        } else {
            t2[0] = t2[1] = t2[2] = t2[3] = __float2half2_rn(1.f);
        }

        const uint32_t* B = Bs[b];
#pragma unroll
        for (int kt = 0; kt < 4; ++kt) {
            __half2 a[2][4];
#pragma unroll
            for (int m = 0; m < 2; ++m) {
                a[m][0] = __hmul2(*(const __half2*)&hh[m][0][2 * kt + 0], t2[2 * m + 0]);
                a[m][1] = __hmul2(*(const __half2*)&hh[m][1][2 * kt + 0], t2[2 * m + 1]);
                a[m][2] = __hmul2(*(const __half2*)&hh[m][0][2 * kt + 1], t2[2 * m + 0]);
                a[m][3] = __hmul2(*(const __half2*)&hh[m][1][2 * kt + 1], t2[2 * m + 1]);
            }
            const uint32_t* Brow = B + (kt * 8 + tig) * BPAD + g;
#pragma unroll
            for (int nt = 0; nt < 8; ++nt) {
                uint32_t b0 = Brow[nt * 8];
                uint32_t b1 = Brow[nt * 8 + 4 * BPAD];
                mma16(C[0][nt], reinterpret_cast<const uint32_t*>(a[0]), b0, b1);
                mma16(C[1][nt], reinterpret_cast<const uint32_t*>(a[1]), b0, b1);
            }
        }
        __syncthreads();
    }

    // epilogue: scatter-add to agg[dst]
    const int ebase = subtile * 128 + wl * 32 + g;
#pragma unroll
    for (int m = 0; m < 2; ++m) {
        int d0 = g_dst[ebase + m * 16];
        int d1 = g_dst[ebase + m * 16 + 8];
        float* p0 = agg + (size_t)d0 * 64 + 2 * tig;
        float* p1 = agg + (size_t)d1 * 64 + 2 * tig;
#pragma unroll
        for (int nt = 0; nt < 8; ++nt) {
            atomicAdd(p0 + nt * 8 + 0, C[m][nt][0]);
            atomicAdd(p0 + nt * 8 + 1, C[m][nt][1]);
            atomicAdd(p1 + nt * 8 + 0, C[m][nt][2]);
            atomicAdd(p1 + nt * 8 + 1, C[m][nt][3]);
        }
    }
}

// ---------------- node update: h_out = lrelu(agg + h_in @ root + bias) ----------------
__global__ void node_update_kernel(const float* __restrict__ hin, const float* __restrict__ agg,
                                   const float* __restrict__ root, const float* __restrict__ bias,
                                   float* __restrict__ hout) {
    int id = blockIdx.x * blockDim.x + threadIdx.x;
    if (id >= N_NODES * HID) return;
    int n = id >> 6, o = id & 63;
    float acc = bias[o] + agg[id];
    const float* hr = hin + (size_t)n * 64;
#pragma unroll 8
    for (int i = 0; i < 64; ++i) acc += hr[i] * root[i * 64 + o];
    hout[id] = lrelu(acc);
}

// ---------------- global add pool ----------------
__global__ void pool_kernel(const float* __restrict__ h) {
    int id = blockIdx.x * blockDim.x + threadIdx.x;
    if (id >= N_NODES * HID) return;
    int n = id >> 6, o = id & 63;
    atomicAdd(&g_hg[g_bat[n] * 64 + o], h[id]);
}

// ---------------- readout head ----------------
__global__ void head_kernel(const float* __restrict__ fc1w, const float* __restrict__ fc1b,
                            const float* __restrict__ fc2w, const float* __restrict__ fc2b,
                            float* __restrict__ out) {
    __shared__ float hs[N_GRAPHS * HID];
    int g = threadIdx.x;
    for (int i = g; i < N_GRAPHS * HID; i += 64) hs[i] = g_hg[i];
    __syncthreads();
    float acc = fc2b[0];
#pragma unroll 4
    for (int j = 0; j < 32; ++j) {
        float s = fc1b[j];
#pragma unroll 8
        for (int i = 0; i < 64; ++i) s += hs[g * 64 + i] * fc1w[i * 32 + j];
        acc += lrelu(s) * fc2w[j];
    }
    out[g] = acc;
}

// ---------------- launch ----------------
extern "C" void kernel_launch(void* const* d_in, const int* in_sizes, int n_in,
                              void* d_out, int out_size) {
    const float* x     = (const float*)d_in[0];
    const void*  ei    = d_in[1];
    const float* ea    = (const float*)d_in[2];
    const void*  bat   = d_in[3];
    const float* nfc_w = (const float*)d_in[4];
    const float* nfc_b = (const float*)d_in[5];
    const float* e1w1  = (const float*)d_in[6];
    const float* e1b1  = (const float*)d_in[7];
    const float* e1w2  = (const float*)d_in[8];
    const float* e1b2  = (const float*)d_in[9];
    const float* root1 = (const float*)d_in[10];
    const float* bias1 = (const float*)d_in[11];
    const float* e2w1  = (const float*)d_in[12];
    const float* e2b1  = (const float*)d_in[13];
    const float* e2w2  = (const float*)d_in[14];
    const float* e2b2  = (const float*)d_in[15];
    const float* root2 = (const float*)d_in[16];
    const float* bias2 = (const float*)d_in[17];
    const float* fc1w  = (const float*)d_in[18];
    const float* fc1b  = (const float*)d_in[19];
    const float* fc2w  = (const float*)d_in[20];
    const float* fc2b  = (const float*)d_in[21];
    float* out = (float*)d_out;

    float *h0, *h1, *agg, *tt1, *tt2, *hg;
    uint32_t *bpp, *hsth;
    cudaGetSymbolAddress((void**)&h0, g_h0);
    cudaGetSymbolAddress((void**)&h1, g_h1);
    cudaGetSymbolAddress((void**)&agg, g_agg);
    cudaGetSymbolAddress((void**)&tt1, g_tt1);
    cudaGetSymbolAddress((void**)&tt2, g_tt2);
    cudaGetSymbolAddress((void**)&hg, g_hg);
    cudaGetSymbolAddress((void**)&bpp, g_bprep);
    cudaGetSymbolAddress((void**)&hsth, g_hsth);

    convert_idx_kernel<<<256, 256>>>(ei, bat);
    node_enc_kernel<<<N_NODES / 16, 256>>>(x, nfc_w, nfc_b, h0);
    bprep2_kernel<<<(2 * NSLICE * 2048 + 255) / 256, 256>>>(e1w2, e1b2, e2w2, e2b2, bpp);
    edge_mlp2_kernel<<<NTILES, 256>>>(ea, e1w1, e1b1, e2w1, e2b1, tt1, tt2);

    // layer 1
    gather_kernel<<<N_EDGES * 32 / 256, 256>>>(h0, hsth);
    zero_kernel<<<(N_NODES * HID + 255) / 256, 256>>>(agg, N_NODES * HID);
    msg_mma_kernel<<<NTILES / 2, 256>>>(tt1, hsth, bpp, agg);
    node_update_kernel<<<(N_NODES * HID + 255) / 256, 256>>>(h0, agg, root1, bias1, h1);

    // layer 2
    gather_kernel<<<N_EDGES * 32 / 256, 256>>>(h1, hsth);
    zero_kernel<<<(N_NODES * HID + 255) / 256, 256>>>(agg, N_NODES * HID);
    msg_mma_kernel<<<NTILES / 2, 256>>>(tt2, hsth, bpp + (size_t)NSLICE * BSLICE, agg);
    node_update_kernel<<<(N_NODES * HID + 255) / 256, 256>>>(h1, agg, root2, bias2, h0);

    // pool + head
    zero_kernel<<<(N_GRAPHS * HID + 255) / 256, 256>>>(hg, N_GRAPHS * HID);
    pool_kernel<<<(N_NODES * HID + 255) / 256, 256>>>(h0);
    head_kernel<<<1, 64>>>(fc1w, fc1b, fc2w, fc2b, out);
}